// round 8
// baseline (speedup 1.0000x reference)
#include <cuda_runtime.h>
#include <math.h>

#define TOPK     64
#define NBINS    65536
#define NCHUNK   256
#define MAXCAND  4096
#define TPB      512           // 16 warps
#define NBLOCKS  296           // 2 per SM, persistent
#define DDIM     512

__device__ float        g_alpha[262144];
__device__ unsigned int g_hist[NBINS];     // fkey >> 16 (fine only)
__device__ unsigned int g_done;            // zero-init; reset each run

// order-preserving float -> uint key
__device__ __forceinline__ unsigned int fkey(float f) {
    unsigned int b = __float_as_uint(f);
    return (b & 0x80000000u) ? ~b : (b | 0x80000000u);
}

__global__ void __launch_bounds__(TPB, 2)
fused_kernel(const float* __restrict__ v,
             const float* __restrict__ vs,
             const float* __restrict__ scores,
             float* __restrict__ out, int N) {
    __shared__ float sv[DDIM];
    const int tid  = threadIdx.x;
    const int lane = tid & 31;
    const int warp = tid >> 5;

    for (int i = tid; i < DDIM; i += TPB) sv[i] = v[i];
    __syncthreads();

    const float4* vv4 = (const float4*)sv;
    const int gwarp  = blockIdx.x * (TPB / 32) + warp;
    const int nwarps = gridDim.x * (TPB / 32);

    // ------------- phase 1: persistent matvec, 2 rows per iteration ----------
    for (int r0 = gwarp; r0 < N; r0 += 2 * nwarps) {
        int r1 = r0 + nwarps;

        // 8 independent LDG.128 up front (4 KB in flight per warp)
        const float4* p0 = (const float4*)(vs + (size_t)r0 * DDIM);
        float4 x00 = p0[lane +  0];
        float4 x01 = p0[lane + 32];
        float4 x02 = p0[lane + 64];
        float4 x03 = p0[lane + 96];
        float4 x10, x11, x12, x13;
        if (r1 < N) {
            const float4* p1 = (const float4*)(vs + (size_t)r1 * DDIM);
            x10 = p1[lane +  0];
            x11 = p1[lane + 32];
            x12 = p1[lane + 64];
            x13 = p1[lane + 96];
        }

        // y shared by both rows (transient registers from smem)
        float4 y0 = vv4[lane +  0];
        float4 y1 = vv4[lane + 32];
        float4 y2 = vv4[lane + 64];
        float4 y3 = vv4[lane + 96];

        float a0 = x00.x*y0.x + x00.y*y0.y + x00.z*y0.z + x00.w*y0.w
                 + x01.x*y1.x + x01.y*y1.y + x01.z*y1.z + x01.w*y1.w
                 + x02.x*y2.x + x02.y*y2.y + x02.z*y2.z + x02.w*y2.w
                 + x03.x*y3.x + x03.y*y3.y + x03.z*y3.z + x03.w*y3.w;
        float a1 = 0.f;
        if (r1 < N) {
            a1 = x10.x*y0.x + x10.y*y0.y + x10.z*y0.z + x10.w*y0.w
               + x11.x*y1.x + x11.y*y1.y + x11.z*y1.z + x11.w*y1.w
               + x12.x*y2.x + x12.y*y2.y + x12.z*y2.z + x12.w*y2.w
               + x13.x*y3.x + x13.y*y3.y + x13.z*y3.z + x13.w*y3.w;
        }

        // interleaved butterflies: the two chains overlap latency
#pragma unroll
        for (int o = 16; o; o >>= 1) {
            a0 += __shfl_xor_sync(0xffffffffu, a0, o);
            a1 += __shfl_xor_sync(0xffffffffu, a1, o);
        }

        if (lane == 0) {
            g_alpha[r0] = a0;
            atomicAdd(&g_hist[fkey(a0) >> 16], 1u);
            if (r1 < N) {
                g_alpha[r1] = a1;
                atomicAdd(&g_hist[fkey(a1) >> 16], 1u);
            }
        }
    }

    // ---------------- last-block election ------------------------------------
    __shared__ unsigned int s_isLast;
    __threadfence();
    __syncthreads();
    if (tid == 0)
        s_isLast = (atomicAdd(&g_done, 1u) == gridDim.x - 1) ? 1u : 0u;
    __syncthreads();
    if (!s_isLast) return;
    __threadfence();

    // ---------------- phase 2: coarse sums from fine hist, threshold bin -----
    __shared__ unsigned int sc[NCHUNK];
    {
        const uint4* h4 = (const uint4*)g_hist;
        unsigned int s = 0;
        int base = tid * 32;                      // 32 uint4 = 128 bins
#pragma unroll 8
        for (int j = 0; j < 32; j++) {
            uint4 u = h4[base + j];
            s += u.x + u.y + u.z + u.w;
        }
        __shared__ unsigned int half[TPB];
        half[tid] = s;
        __syncthreads();
        if (tid < NCHUNK) sc[tid] = half[2 * tid] + half[2 * tid + 1];
        __syncthreads();
    }

    __shared__ int s_chunk;
    __shared__ unsigned int s_above;
    __shared__ unsigned int s_tb;
    if (tid == 0) {
        unsigned int cum = 0;
        int c;
        for (c = 255; c >= 0; c--) {
            if (cum + sc[c] >= (unsigned int)TOPK) break;
            cum += sc[c];
        }
        if (c < 0) c = 0;
        s_chunk = c;
        s_above = cum;
    }
    __syncthreads();
    __shared__ unsigned int sf[256];
    if (tid < 256) sf[tid] = g_hist[s_chunk * 256 + tid];
    __syncthreads();
    if (tid == 0) {
        unsigned int cum = s_above;
        int b;
        for (b = 255; b >= 0; b--) {
            cum += sf[b];
            if (cum >= (unsigned int)TOPK) break;
        }
        if (b < 0) b = 0;
        s_tb = (unsigned int)(s_chunk * 256 + b);
    }
    __syncthreads();
    unsigned int tb = s_tb;

    // ---------------- phase 3: scan alpha (L2-hot), candidates to smem -------
    __shared__ float sval[MAXCAND];
    __shared__ int   sidx[MAXCAND];
    __shared__ int   s_cand;
    if (tid == 0) s_cand = 0;
    __syncthreads();

    int n4 = N >> 2;
    for (int i = tid; i < n4; i += TPB) {
        float4 a = ((const float4*)g_alpha)[i];
        int base = i << 2;
        if ((fkey(a.x) >> 16) >= tb) {
            int p = atomicAdd(&s_cand, 1);
            if (p < MAXCAND) { sval[p] = a.x; sidx[p] = base + 0; }
        }
        if ((fkey(a.y) >> 16) >= tb) {
            int p = atomicAdd(&s_cand, 1);
            if (p < MAXCAND) { sval[p] = a.y; sidx[p] = base + 1; }
        }
        if ((fkey(a.z) >> 16) >= tb) {
            int p = atomicAdd(&s_cand, 1);
            if (p < MAXCAND) { sval[p] = a.z; sidx[p] = base + 2; }
        }
        if ((fkey(a.w) >> 16) >= tb) {
            int p = atomicAdd(&s_cand, 1);
            if (p < MAXCAND) { sval[p] = a.w; sidx[p] = base + 3; }
        }
    }
    if (tid == 0) {
        for (int i = n4 << 2; i < N; i++) {
            float a = g_alpha[i];
            if ((fkey(a) >> 16) >= tb) {
                int p = atomicAdd(&s_cand, 1);
                if (p < MAXCAND) { sval[p] = a; sidx[p] = i; }
            }
        }
    }
    __syncthreads();
    int C = s_cand;
    if (C > MAXCAND) C = MAXCAND;

    // ---------------- phase 4: max, rank-select, softmax, weighted sum -------
    __shared__ float r1[TPB];
    __shared__ float r2[TPB];

    float m = -INFINITY;
    for (int i = tid; i < C; i += TPB) m = fmaxf(m, sval[i]);
    r1[tid] = m;
    __syncthreads();
    for (int s = TPB / 2; s; s >>= 1) {
        if (tid < s) r1[tid] = fmaxf(r1[tid], r1[tid + s]);
        __syncthreads();
    }
    m = r1[0];
    __syncthreads();

    float se = 0.f, acc = 0.f;
    for (int i = tid; i < C; i += TPB) {
        float vi = sval[i];
        unsigned int ki = fkey(vi);
        int rank = 0;
        for (int j = 0; j < C; j++) {
            unsigned int kj = fkey(sval[j]);
            rank += (kj > ki) || (kj == ki && j < i);
        }
        if (rank < TOPK) {
            float e = __expf(vi - m);
            se += e;
            acc += e * scores[sidx[i]];
        }
    }
    r1[tid] = se;
    r2[tid] = acc;
    __syncthreads();
    for (int s = TPB / 2; s; s >>= 1) {
        if (tid < s) {
            r1[tid] += r1[tid + s];
            r2[tid] += r2[tid + s];
        }
        __syncthreads();
    }
    if (tid == 0) out[0] = r2[0] / r1[0];

    // ---------------- phase 5: reset scratch for next graph replay -----------
    if (tid < NCHUNK) {
        if (sc[tid] != 0u) {
            uint4 z = make_uint4(0u, 0u, 0u, 0u);
            uint4* dst = (uint4*)&g_hist[tid * 256];
#pragma unroll
            for (int j = 0; j < 64; j++) dst[j] = z;
        }
    }
    if (tid == 0) g_done = 0u;
}

// ---------------- launch ------------------------------------------------------
extern "C" void kernel_launch(void* const* d_in, const int* in_sizes, int n_in,
                              void* d_out, int out_size) {
    const float* v      = (const float*)d_in[0];
    const float* vs     = (const float*)d_in[1];
    const float* scores = (const float*)d_in[2];
    float* out = (float*)d_out;
    int N = in_sizes[2];
    (void)n_in; (void)out_size;

    fused_kernel<<<NBLOCKS, TPB>>>(v, vs, scores, out, N);
}